// round 15
// baseline (speedup 1.0000x reference)
#include <cuda_runtime.h>
#include <cuda_bf16.h>
#include <cstdint>

// DynamicMaskHead: 128 instances, MLP 10 -> 8 -> 8 -> 1 over 160x160 px (fp32).
// Persistent single-wave kernel: 740 CTAs (5/SM), each owning a contiguous run
// of 8-9 tiles (512 px). R14: features loaded DIRECTLY into registers with
// front-batched LDG.128 (no cp.async smem ring -> no smem write+read round
// trip through L1TEX). Weights (<=2 instances per run) preloaded once into
// smem, duplicated float2 halves so LDS.64 feeds fma.rn.f32x2 directly.

#define NINST 128
#define CIN   10
#define CMID  8
#define HW    25600
#define HW4   (HW / 4)
#define TPB   128
#define TILE4 128                       // float4 per tile (512 px)
#define TILES_PER_INST 50
#define NCTA 740                        // 5 per SM, one wave

__device__ __forceinline__ float2 ffma2(float2 a, float2 b, float2 c) {
    float2 d;
    asm("fma.rn.f32x2 %0, %1, %2, %3;"
        : "=l"(reinterpret_cast<unsigned long long&>(d))
        : "l"(reinterpret_cast<unsigned long long&>(a)),
          "l"(reinterpret_cast<unsigned long long&>(b)),
          "l"(reinterpret_cast<unsigned long long&>(c)));
    return d;
}

__device__ __forceinline__ float2 relu2(float2 a) {
    return make_float2(fmaxf(a.x, 0.0f), fmaxf(a.y, 0.0f));
}

__global__ void __launch_bounds__(TPB, 5)
mask_head_kernel(const float* __restrict__ feat,
                 const float* __restrict__ params,
                 float* __restrict__ out) {
    // Double-buffered weight sets (a CTA's run spans <= 2 instances).
    __shared__ float2 w0s[2][CMID * CIN];
    __shared__ float2 w1s[2][CMID * CMID];
    __shared__ float2 w2s[2][CMID];
    __shared__ float2 b0s[2][CMID];
    __shared__ float2 b1s[2][CMID];
    __shared__ float2 b2s[2];

    const int tid = threadIdx.x;
    const int b   = blockIdx.x;

    // 6400 tiles over 740 CTAs: first 480 get 9, remaining 260 get 8.
    int first, count;
    if (b < 480) { first = b * 9;                count = 9; }
    else         { first = 4320 + (b - 480) * 8; count = 8; }

    const int inst0 = first / TILES_PER_INST;
    const int inst1 = (first + count - 1) / TILES_PER_INST;  // inst0 or inst0+1

    const float4* fin4 = reinterpret_cast<const float4*>(feat);
    float4* out4 = reinterpret_cast<float4*>(out);

    // Preload both weight sets.
    for (int i = tid; i < 169; i += TPB) {
        float va = params[inst0 * 169 + i];
        float vb = params[inst1 * 169 + i];
        float2 a2  = make_float2(va, va);
        float2 b2v = make_float2(vb, vb);
        if      (i < 80)  { w0s[0][i]       = a2; w0s[1][i]       = b2v; }
        else if (i < 144) { w1s[0][i - 80]  = a2; w1s[1][i - 80]  = b2v; }
        else if (i < 152) { w2s[0][i - 144] = a2; w2s[1][i - 144] = b2v; }
        else if (i < 160) { b0s[0][i - 152] = a2; b0s[1][i - 152] = b2v; }
        else if (i < 168) { b1s[0][i - 160] = a2; b1s[1][i - 160] = b2v; }
        else              { b2s[0]          = a2; b2s[1]          = b2v; }
    }
    __syncthreads();   // only block barrier in the kernel

    for (int i = 0; i < count; i++) {
        const int item = first + i;
        const int inst = item / TILES_PER_INST;
        const int tile = item % TILES_PER_INST;
        const int wsel = (inst != inst0) ? 1 : 0;

        const float4* g = fin4 + inst * CIN * HW4 + tile * TILE4 + tid;
        const float2* w0p = w0s[wsel];
        const float2* w1p = w1s[wsel];
        const float2* w2p = w2s[wsel];
        const float2* b0p = b0s[wsel];
        const float2* b1p = b1s[wsel];

        // ---- Front-batched loads: all 10 LDG.128 issued before any FMA ----
        float2 x[CIN][2];
#pragma unroll
        for (int k = 0; k < CIN; k++) {
            float4 v = g[k * HW4];
            x[k][0] = make_float2(v.x, v.y);
            x[k][1] = make_float2(v.z, v.w);
        }

        // ---- Layer 0 (10 -> 8, ReLU), 4 px = 2 f32x2 lanes ----
        float2 h0[CMID][2];
#pragma unroll
        for (int o = 0; o < CMID; o++) {
            float2 bb = b0p[o];
            h0[o][0] = bb; h0[o][1] = bb;
        }
#pragma unroll
        for (int k = 0; k < CIN; k++) {
#pragma unroll
            for (int o = 0; o < CMID; o++) {
                float2 w = w0p[o * CIN + k];
                h0[o][0] = ffma2(w, x[k][0], h0[o][0]);
                h0[o][1] = ffma2(w, x[k][1], h0[o][1]);
            }
        }
#pragma unroll
        for (int o = 0; o < CMID; o++) {
            h0[o][0] = relu2(h0[o][0]);
            h0[o][1] = relu2(h0[o][1]);
        }

        // ---- Layers 1+2 fused ----
        float2 acc0, acc1;
        {
            float2 bb = b2s[wsel];
            acc0 = bb; acc1 = bb;
        }
#pragma unroll
        for (int o = 0; o < CMID; o++) {
            float2 bb = b1p[o];
            float2 t0 = bb, t1 = bb;
#pragma unroll
            for (int k = 0; k < CMID; k++) {
                float2 w = w1p[o * CMID + k];
                t0 = ffma2(w, h0[k][0], t0);
                t1 = ffma2(w, h0[k][1], t1);
            }
            float2 w2 = w2p[o];
            acc0 = ffma2(w2, relu2(t0), acc0);
            acc1 = ffma2(w2, relu2(t1), acc1);
        }

        out4[inst * HW4 + tile * TILE4 + tid] =
            make_float4(acc0.x, acc0.y, acc1.x, acc1.y);
    }
}

extern "C" void kernel_launch(void* const* d_in, const int* in_sizes, int n_in,
                              void* d_out, int out_size) {
    const float* feat   = (const float*)d_in[0];
    const float* params = (const float*)d_in[1];
    float* out          = (float*)d_out;

    mask_head_kernel<<<NCTA, TPB>>>(feat, params, out);
}